// round 5
// baseline (speedup 1.0000x reference)
#include <cuda_runtime.h>

// RankingLoss over all pairs, N=8192, single fused kernel.
// loss = sum_{i,j: dur_i<dur_j, ev_i==1} max(1-(p_i-p_j),0) / count (0 if count==0).
//
// Block = 256 threads, 256 i-rows, 256-wide j-chunk -> 1024 blocks (occupancy).
// Event rows block-locally compacted (order-preserving ballot scan, deterministic).
// Inner loop accumulates {penalty, 1.0} with one predicated add.rn.f32x2.
// Last-arriving block reduces all partials in fixed order and writes the output.

#define NN 8192
#define TPB 256
#define IG  256                 // i-rows per block
#define JC  256                 // j-cols per block
#define GX  (NN / JC)           // 32
#define GYI (NN / IG)           // 32
#define NBLK (GX * GYI)         // 1024

__device__ float2       g_p[NBLK];     // {sum, count} partials
__device__ unsigned int g_tick = 0u;

// One pair: if (dur < dj) acc2 += {max(c+pj,0), 1.0}  (packed f32x2)
#define PAIR(dj, pj, acc)                                                     \
    do {                                                                      \
        const float t_ = fmaxf(c + (pj), 0.0f);                               \
        asm("{\n\t"                                                           \
            ".reg .pred p;\n\t"                                               \
            ".reg .b64 v;\n\t"                                                \
            "setp.lt.f32 p, %1, %2;\n\t"                                      \
            "mov.b64 v, {%3, %4};\n\t"                                        \
            "@p add.rn.f32x2 %0, %0, v;\n\t"                                  \
            "}"                                                               \
            : "+l"(acc)                                                       \
            : "f"(dur), "f"(dj), "f"(t_), "f"(one));                          \
    } while (0)

__global__ void __launch_bounds__(TPB)
pair_kernel(const float* __restrict__ preds, const float* __restrict__ targets,
            float* __restrict__ out)
{
    __shared__ float4 tile4[JC / 2];   // {dur_2t, p_2t, dur_2t+1, p_2t+1}
    __shared__ float  sdur[IG];        // compacted event-row durations
    __shared__ float  scst[IG];        // compacted 1 - p_i
    __shared__ int    wcnt[TPB / 32];
    __shared__ float2 red[TPB];
    __shared__ int    last_flag;

    const int tid  = threadIdx.x;
    const int wid  = tid >> 5;
    const int lane = tid & 31;
    const int i    = blockIdx.y * IG + tid;
    const int j0   = blockIdx.x * JC;

    // --- load my i-row, ballot-compact event rows (order preserving) ---
    const float di = targets[2 * i];
    const float ei = targets[2 * i + 1];
    const float pi = preds[i];
    const bool  f  = (ei == 1.0f);
    const unsigned bm = __ballot_sync(0xffffffffu, f);
    if (lane == 0) wcnt[wid] = __popc(bm);

    // --- cooperative j-tile load (packed float4) ---
    for (int t = tid; t < JC / 2; t += TPB) {
        const int j = j0 + 2 * t;
        tile4[t] = make_float4(targets[2 * j],     preds[j],
                               targets[2 * j + 2], preds[j + 1]);
    }
    __syncthreads();

    int base = 0, m = 0;
    #pragma unroll
    for (int w = 0; w < TPB / 32; ++w) {
        const int c = wcnt[w];
        if (w < wid) base += c;
        m += c;
    }
    if (f) {
        const int pos = base + __popc(bm & ((1u << lane) - 1u));
        sdur[pos] = di;
        scst[pos] = 1.0f - pi;
    }
    __syncthreads();

    // --- main loop: threads [0, m) each own one compacted event row ---
    unsigned long long a0 = 0ull, a1 = 0ull, a2 = 0ull, a3 = 0ull;
    if (tid < m) {
        const float dur = sdur[tid];
        const float c   = scst[tid];
        const float one = 1.0f;
        #pragma unroll 4
        for (int t = 0; t < JC / 2; t += 2) {
            const float4 A = tile4[t];
            const float4 B = tile4[t + 1];
            PAIR(A.x, A.y, a0);
            PAIR(A.z, A.w, a1);
            PAIR(B.x, B.y, a2);
            PAIR(B.z, B.w, a3);
        }
    }

    // --- deterministic block reduction of {sum, count} ---
    float2 f0 = *reinterpret_cast<float2*>(&a0);
    float2 f1 = *reinterpret_cast<float2*>(&a1);
    float2 f2 = *reinterpret_cast<float2*>(&a2);
    float2 f3 = *reinterpret_cast<float2*>(&a3);
    red[tid] = make_float2((f0.x + f1.x) + (f2.x + f3.x),
                           (f0.y + f1.y) + (f2.y + f3.y));
    __syncthreads();
    #pragma unroll
    for (int o = TPB / 2; o > 0; o >>= 1) {
        if (tid < o) {
            red[tid].x += red[tid + o].x;
            red[tid].y += red[tid + o].y;
        }
        __syncthreads();
    }

    // --- publish partial; last-arriving block reduces everything ---
    if (tid == 0) {
        g_p[blockIdx.y * GX + blockIdx.x] = red[0];
        __threadfence();
        const unsigned t = atomicAdd(&g_tick, 1u);
        last_flag = (t == NBLK - 1u) ? 1 : 0;
    }
    __syncthreads();

    if (last_flag) {
        __threadfence();
        // 1024 partials -> 256 threads x 4 in fixed order: deterministic.
        float2 p0 = g_p[tid];
        float2 p1 = g_p[tid + TPB];
        float2 p2 = g_p[tid + 2 * TPB];
        float2 p3 = g_p[tid + 3 * TPB];
        red[tid] = make_float2((p0.x + p1.x) + (p2.x + p3.x),
                               (p0.y + p1.y) + (p2.y + p3.y));
        __syncthreads();
        #pragma unroll
        for (int o = TPB / 2; o > 0; o >>= 1) {
            if (tid < o) {
                red[tid].x += red[tid + o].x;
                red[tid].y += red[tid + o].y;
            }
            __syncthreads();
        }
        if (tid == 0) {
            out[0] = (red[0].y > 0.0f) ? (red[0].x / red[0].y) : 0.0f;
            g_tick = 0u;   // reset for next graph replay
        }
    }
}

extern "C" void kernel_launch(void* const* d_in, const int* in_sizes, int n_in,
                              void* d_out, int out_size)
{
    const float* preds   = (const float*)d_in[0];   // [8192]
    const float* targets = (const float*)d_in[1];   // [8192,2] {dur, ev}
    float* out = (float*)d_out;

    dim3 grid(GX, GYI);
    pair_kernel<<<grid, TPB>>>(preds, targets, out);
}

// round 6
// speedup vs baseline: 1.2226x; 1.2226x over previous
#include <cuda_runtime.h>

// RankingLoss over all pairs, N=8192, single fused kernel.
// loss = sum_{i,j: dur_i<dur_j, ev_i==1} max(1-(p_i-p_j),0) / count (0 if count==0).
//
// Block = 256 threads owns 512 i-rows (so ~256 compacted event rows -> ALL warps
// work) and one 256-wide j-chunk. Event rows block-locally compacted with an
// order-preserving ballot scan (deterministic). Last-arriving block reduces all
// partials in fixed order and writes the output.

#define NN 8192
#define TPB 256
#define IG  512                 // i-rows per block (2 compaction rounds)
#define JC  256                 // j-cols per block
#define GX  (NN / JC)           // 32
#define GYI (NN / IG)           // 16
#define NBLK (GX * GYI)         // 512
#define NW  (TPB / 32)          // 8 warps

__device__ float        g_s[NBLK];
__device__ unsigned int g_c[NBLK];
__device__ unsigned int g_tick = 0u;

__global__ void __launch_bounds__(TPB)
pair_kernel(const float* __restrict__ preds, const float* __restrict__ targets,
            float* __restrict__ out)
{
    __shared__ float4 tile4[JC / 2];   // {dur_2t, p_2t, dur_2t+1, p_2t+1}
    __shared__ float  sdur[IG];        // compacted event-row durations
    __shared__ float  scst[IG];        // compacted 1 - p_i
    __shared__ int    wcnt[2 * NW];    // per-warp event counts, 2 rounds
    __shared__ float        rs[TPB];
    __shared__ unsigned int rc[TPB];
    __shared__ int    last_flag;

    const int tid  = threadIdx.x;
    const int wid  = tid >> 5;
    const int lane = tid & 31;
    const int i0   = blockIdx.y * IG + tid;        // round-0 row
    const int i1   = i0 + TPB;                     // round-1 row
    const int j0   = blockIdx.x * JC;

    // --- load both i-rows, ballot per round ---
    const float d0 = targets[2 * i0];
    const float e0 = targets[2 * i0 + 1];
    const float p0 = preds[i0];
    const float d1 = targets[2 * i1];
    const float e1 = targets[2 * i1 + 1];
    const float p1 = preds[i1];
    const bool  f0 = (e0 == 1.0f);
    const bool  f1 = (e1 == 1.0f);
    const unsigned bm0 = __ballot_sync(0xffffffffu, f0);
    const unsigned bm1 = __ballot_sync(0xffffffffu, f1);
    if (lane == 0) {
        wcnt[wid]      = __popc(bm0);
        wcnt[NW + wid] = __popc(bm1);
    }

    // --- cooperative j-tile load (packed float4) ---
    for (int t = tid; t < JC / 2; t += TPB) {
        const int j = j0 + 2 * t;
        tile4[t] = make_float4(targets[2 * j],     preds[j],
                               targets[2 * j + 2], preds[j + 1]);
    }
    __syncthreads();

    // --- order-preserving prefix over 16 warp-counts ---
    int base0 = 0, base1 = 0, m = 0;
    #pragma unroll
    for (int w = 0; w < NW; ++w) {
        const int c = wcnt[w];
        if (w < wid) base0 += c;
        base1 += c;                       // round-1 bases start after all round-0
        m += c;
    }
    #pragma unroll
    for (int w = 0; w < NW; ++w) {
        const int c = wcnt[NW + w];
        if (w < wid) base1 += c;
        m += c;
    }
    if (f0) {
        const int pos = base0 + __popc(bm0 & ((1u << lane) - 1u));
        sdur[pos] = d0;
        scst[pos] = 1.0f - p0;
    }
    if (f1) {
        const int pos = base1 + __popc(bm1 & ((1u << lane) - 1u));
        sdur[pos] = d1;
        scst[pos] = 1.0f - p1;
    }
    __syncthreads();

    // --- main loop: all threads grid-stride over compacted rows ---
    float s0 = 0.0f, s1 = 0.0f, s2 = 0.0f, s3 = 0.0f;
    unsigned int cnt = 0u;
    for (int r = tid; r < m; r += TPB) {
        const float dur = sdur[r];
        const float c   = scst[r];
        #pragma unroll 4
        for (int t = 0; t < JC / 2; t += 2) {
            const float4 A = tile4[t];
            const float4 B = tile4[t + 1];
            if (dur < A.x) { s0 += fmaxf(c + A.y, 0.0f); cnt++; }
            if (dur < A.z) { s1 += fmaxf(c + A.w, 0.0f); cnt++; }
            if (dur < B.x) { s2 += fmaxf(c + B.y, 0.0f); cnt++; }
            if (dur < B.z) { s3 += fmaxf(c + B.w, 0.0f); cnt++; }
        }
    }

    // --- deterministic block reduction ---
    rs[tid] = (s0 + s1) + (s2 + s3);
    rc[tid] = cnt;
    __syncthreads();
    #pragma unroll
    for (int o = TPB / 2; o > 0; o >>= 1) {
        if (tid < o) { rs[tid] += rs[tid + o]; rc[tid] += rc[tid + o]; }
        __syncthreads();
    }

    // --- publish partial; last-arriving block reduces everything ---
    if (tid == 0) {
        const int slot = blockIdx.y * GX + blockIdx.x;
        g_s[slot] = rs[0];
        g_c[slot] = rc[0];
        __threadfence();
        const unsigned t = atomicAdd(&g_tick, 1u);
        last_flag = (t == NBLK - 1u) ? 1 : 0;
    }
    __syncthreads();

    if (last_flag) {
        __threadfence();
        // 512 partials -> 256 threads x 2, fixed order: deterministic.
        rs[tid] = g_s[tid] + g_s[tid + TPB];
        rc[tid] = g_c[tid] + g_c[tid + TPB];
        __syncthreads();
        #pragma unroll
        for (int o = TPB / 2; o > 0; o >>= 1) {
            if (tid < o) { rs[tid] += rs[tid + o]; rc[tid] += rc[tid + o]; }
            __syncthreads();
        }
        if (tid == 0) {
            out[0] = (rc[0] > 0u) ? (rs[0] / (float)rc[0]) : 0.0f;
            g_tick = 0u;   // reset for next graph replay
        }
    }
}

extern "C" void kernel_launch(void* const* d_in, const int* in_sizes, int n_in,
                              void* d_out, int out_size)
{
    const float* preds   = (const float*)d_in[0];   // [8192]
    const float* targets = (const float*)d_in[1];   // [8192,2] {dur, ev}
    float* out = (float*)d_out;

    dim3 grid(GX, GYI);
    pair_kernel<<<grid, TPB>>>(preds, targets, out);
}